// round 5
// baseline (speedup 1.0000x reference)
#include <cuda_runtime.h>
#include <math.h>
#include <stdint.h>

#define K_CL 1024
#define DM   256
#define NPX  65536
#define NISO 12
#define RBLK 304
#define CHUNK 216      // positions per reduce block (304*216 >= 65536)
#define HBLK 64        // hist/scatter blocks per matrix
#define HCH  (NPX / HBLK)   // 1024 rows per hist/scatter block

typedef unsigned long long u64;

__device__ __forceinline__ u64 pack2(float lo, float hi) {
    u64 r;
    asm("mov.b64 %0, {%1, %2};" : "=l"(r)
        : "r"(__float_as_uint(lo)), "r"(__float_as_uint(hi)));
    return r;
}
__device__ __forceinline__ void unpack2(u64 v, float& lo, float& hi) {
    unsigned a, b;
    asm("mov.b64 {%0, %1}, %2;" : "=r"(a), "=r"(b) : "l"(v));
    lo = __uint_as_float(a); hi = __uint_as_float(b);
}
__device__ __forceinline__ u64 fma2(u64 a, u64 b, u64 c) {
    u64 d;
    asm("fma.rn.f32x2 %0, %1, %2, %3;" : "=l"(d) : "l"(a), "l"(b), "l"(c));
    return d;
}

// ---------------- device scratch ----------------
__device__ float g_part[2 * RBLK * 15 * K_CL];
__device__ float g_S[2 * 15 * K_CL];
__device__ int   g_bh[2 * HBLK * NISO];      // per-block bucket counts
__device__ int   g_boff[2 * (NISO + 1)];     // bucket offsets per matrix
__device__ int   g_bbase[2 * HBLK * NISO];   // per-block scatter bases
__device__ int   g_order[2 * NPX];           // row indices grouped by bucket
__device__ float g_GU[K_CL * 32];
__device__ float g_GV[K_CL * 32];
__device__ float g_HA[K_CL * 32];
__device__ float g_HB[K_CL * 32];
__device__ float g_QC[K_CL * 2];
__device__ float g_KC[K_CL * 2];
__device__ float g_R[K_CL * K_CL];
__device__ float g_L[K_CL * K_CL];
__device__ float g_AO[K_CL * DM];
__device__ float g_X[K_CL * DM];
__device__ float g_F1[K_CL * 4 * DM];
__device__ float g_F2[K_CL * DM];

// ---------------- sort step 1: per-block bucket histogram (ballot, no atomics) --------
__launch_bounds__(256)
__global__ void hist_k(const int* __restrict__ qiso, const int* __restrict__ kiso)
{
    const int mat = blockIdx.y, b = blockIdx.x;
    const int* __restrict__ iso = mat ? kiso : qiso;
    const int base = b * HCH;
    const int lane = threadIdx.x & 31, w = threadIdx.x >> 5;

    int wcnt[NISO];
    #pragma unroll
    for (int c = 0; c < NISO; c++) wcnt[c] = 0;

    #pragma unroll
    for (int i = 0; i < HCH / 256; i++) {
        int r = base + w * (HCH / 8) + i * 32 + lane;
        int c = __ldg(iso + r) - 1;
        #pragma unroll
        for (int cc = 0; cc < NISO; cc++) {
            unsigned m = __ballot_sync(0xFFFFFFFFu, c == cc);
            wcnt[cc] += __popc(m);
        }
    }
    __shared__ int sw[8][NISO];
    if (lane == 0) {
        #pragma unroll
        for (int cc = 0; cc < NISO; cc++) sw[w][cc] = wcnt[cc];
    }
    __syncthreads();
    if (threadIdx.x < NISO) {
        int c = threadIdx.x, s = 0;
        #pragma unroll
        for (int ww = 0; ww < 8; ww++) s += sw[ww][c];
        g_bh[(mat * HBLK + b) * NISO + c] = s;
    }
}

// ---------------- sort step 2: offsets + per-block bases ----------------
__launch_bounds__(256)
__global__ void offsets_k()
{
    __shared__ int sbh[2 * HBLK * NISO];   // 1536 ints
    __shared__ int sct[2 * NISO];
    __shared__ int sboff[2][NISO + 1];
    const int tid = threadIdx.x;
    for (int i = tid; i < 2 * HBLK * NISO; i += 256) sbh[i] = g_bh[i];
    __syncthreads();
    if (tid < 2 * NISO) {
        int mat = tid / NISO, c = tid % NISO, s = 0;
        for (int b = 0; b < HBLK; b++) s += sbh[(mat * HBLK + b) * NISO + c];
        sct[tid] = s;
    }
    __syncthreads();
    if (tid < 2) {
        int s = 0;
        for (int c = 0; c < NISO; c++) { sboff[tid][c] = s; s += sct[tid * NISO + c]; }
        sboff[tid][NISO] = s;
    }
    __syncthreads();
    if (tid < 2 * (NISO + 1)) {
        int mat = tid / (NISO + 1), c = tid % (NISO + 1);
        g_boff[tid] = sboff[mat][c];
    }
    if (tid < 2 * NISO) {
        int mat = tid / NISO, c = tid % NISO;
        int s = sboff[mat][c];
        for (int b = 0; b < HBLK; b++) {
            g_bbase[(mat * HBLK + b) * NISO + c] = s;
            s += sbh[(mat * HBLK + b) * NISO + c];
        }
    }
}

// ---------------- sort step 3: deterministic warp-stable scatter ----------------
__launch_bounds__(256)
__global__ void scatter_k(const int* __restrict__ qiso, const int* __restrict__ kiso)
{
    const int mat = blockIdx.y, b = blockIdx.x;
    const int* __restrict__ iso = mat ? kiso : qiso;
    const int base = b * HCH;
    const int lane = threadIdx.x & 31, w = threadIdx.x >> 5;

    // pass 1: warp counts
    int wcnt[NISO];
    #pragma unroll
    for (int c = 0; c < NISO; c++) wcnt[c] = 0;
    #pragma unroll
    for (int i = 0; i < HCH / 256; i++) {
        int r = base + w * (HCH / 8) + i * 32 + lane;
        int c = __ldg(iso + r) - 1;
        #pragma unroll
        for (int cc = 0; cc < NISO; cc++) {
            unsigned m = __ballot_sync(0xFFFFFFFFu, c == cc);
            wcnt[cc] += __popc(m);
        }
    }
    __shared__ int sw[8][NISO];
    __shared__ int swbase[8][NISO];
    if (lane == 0) {
        #pragma unroll
        for (int cc = 0; cc < NISO; cc++) sw[w][cc] = wcnt[cc];
    }
    __syncthreads();
    if (threadIdx.x < NISO) {
        int c = threadIdx.x;
        int s = g_bbase[(mat * HBLK + b) * NISO + c];
        for (int ww = 0; ww < 8; ww++) { swbase[ww][c] = s; s += sw[ww][c]; }
    }
    __syncthreads();

    // pass 2: stable scatter within warp
    int wb[NISO];
    #pragma unroll
    for (int cc = 0; cc < NISO; cc++) wb[cc] = swbase[w][cc];
    unsigned below = (lane == 0) ? 0u : (0xFFFFFFFFu >> (32 - lane));
    #pragma unroll
    for (int i = 0; i < HCH / 256; i++) {
        int r = base + w * (HCH / 8) + i * 32 + lane;
        int c = __ldg(iso + r) - 1;
        #pragma unroll
        for (int cc = 0; cc < NISO; cc++) {
            unsigned m = __ballot_sync(0xFFFFFFFFu, c == cc);
            if (c == cc) {
                int pos = wb[cc] + __popc(m & below);
                g_order[mat * NPX + pos] = r;
            }
            wb[cc] += __popc(m);
        }
    }
}

// ---------------- kernel 1: fused A^T reductions, register-only (HBM bound) --------
__launch_bounds__(256)
__global__ void reduce_k(const float* __restrict__ qA, const float* __restrict__ kA,
                         const float* __restrict__ qco, const float* __restrict__ kco)
{
    __shared__ int    sord[CHUNK];
    __shared__ float2 sco[CHUNK];
    const int tid = threadIdx.x;
    const int bx  = blockIdx.x;
    const int mat = blockIdx.y;
    const float* __restrict__ A    = mat ? kA : qA;
    const float2* __restrict__ co2 = (const float2*)(mat ? kco : qco);

    const int p0 = bx * CHUNK;
    const int p1 = (p0 + CHUNK < NPX) ? p0 + CHUNK : NPX;
    const int cnt = p1 - p0;

    for (int i = tid; i < cnt; i += 256) {
        int row = __ldg(g_order + mat * NPX + p0 + i);
        sord[i] = row;
        sco[i]  = __ldg(co2 + row);
    }
    __syncthreads();

    int bo[NISO + 1];
    #pragma unroll
    for (int c = 0; c <= NISO; c++) bo[c] = g_boff[mat * (NISO + 1) + c];

    const u64 kOne = pack2(1.f, 1.f);
    u64 sx0 = 0, sx1 = 0, sy0 = 0, sy1 = 0, ss0 = 0, ss1 = 0;

    const char* Abase = (const char*)A;
    float* P = g_part + (size_t)(mat * RBLK + bx) * 15 * K_CL;

    #pragma unroll 1
    for (int c = 0; c < NISO; c++) {
        int s = bo[c]     > p0 ? bo[c]     - p0 : 0;
        int e = bo[c + 1] < p1 ? bo[c + 1] - p0 : cnt;
        u64 ac0 = 0, ac1 = 0;
        int i = s;
        for (; i + 4 <= e; i += 4) {
            int r0 = sord[i], r1 = sord[i+1], r2 = sord[i+2], r3 = sord[i+3];
            float2 c0 = sco[i], c1 = sco[i+1], c2 = sco[i+2], c3 = sco[i+3];
            ulonglong2 a0 = *(const ulonglong2*)(Abase + ((size_t)r0 * K_CL + tid * 4) * 4);
            ulonglong2 a1 = *(const ulonglong2*)(Abase + ((size_t)r1 * K_CL + tid * 4) * 4);
            ulonglong2 a2 = *(const ulonglong2*)(Abase + ((size_t)r2 * K_CL + tid * 4) * 4);
            ulonglong2 a3 = *(const ulonglong2*)(Abase + ((size_t)r3 * K_CL + tid * 4) * 4);
            #define ROW(av, cv) do { \
                u64 xx = pack2(cv.x, cv.x), yy = pack2(cv.y, cv.y); \
                sx0 = fma2(av.x, xx, sx0); sx1 = fma2(av.y, xx, sx1); \
                sy0 = fma2(av.x, yy, sy0); sy1 = fma2(av.y, yy, sy1); \
                ss0 = fma2(av.x, kOne, ss0); ss1 = fma2(av.y, kOne, ss1); \
                ac0 = fma2(av.x, kOne, ac0); ac1 = fma2(av.y, kOne, ac1); } while (0)
            ROW(a0, c0); ROW(a1, c1); ROW(a2, c2); ROW(a3, c3);
        }
        for (; i < e; i++) {
            int r0 = sord[i]; float2 c0 = sco[i];
            ulonglong2 a0 = *(const ulonglong2*)(Abase + ((size_t)r0 * K_CL + tid * 4) * 4);
            ROW(a0, c0);
            #undef ROW
        }
        u64* Pu = (u64*)(P + (size_t)(3 + c) * K_CL);
        Pu[tid * 2] = ac0; Pu[tid * 2 + 1] = ac1;
    }

    u64* Px = (u64*)(P + 0 * K_CL);
    u64* Py = (u64*)(P + 1 * K_CL);
    u64* Ps = (u64*)(P + 2 * K_CL);
    Px[tid * 2] = sx0; Px[tid * 2 + 1] = sx1;
    Py[tid * 2] = sy0; Py[tid * 2 + 1] = sy1;
    Ps[tid * 2] = ss0; Ps[tid * 2 + 1] = ss1;
}

// ---------------- kernel 2: reduce partials ----------------
__global__ void reduce2_k()
{
    int idx = blockIdx.x * 256 + threadIdx.x;
    int mat = idx / (15 * K_CL);
    int rem = idx % (15 * K_CL);
    const float* P = g_part + (size_t)mat * RBLK * 15 * K_CL + rem;
    float s = 0.f;
    #pragma unroll 8
    for (int b = 0; b < RBLK; b++) s += P[(size_t)b * 15 * K_CL];
    g_S[idx] = s;
}

// ---------------- kernel 3: per-cluster features ----------------
__global__ void cfeat_k(const float* __restrict__ sensor,
                        const float* __restrict__ g1w, const float* __restrict__ g1b,
                        const float* __restrict__ h1w, const float* __restrict__ h1b)
{
    int k = blockIdx.x * 256 + threadIdx.x;
    float dq[NISO], dkp[NISO];

    float sq  = g_S[(0*15 + 2)*K_CL + k];
    float qcx = g_S[(0*15 + 0)*K_CL + k] / (sq + 1e-6f);
    float qcy = g_S[(0*15 + 1)*K_CL + k] / (sq + 1e-6f);
    float sk  = g_S[(1*15 + 2)*K_CL + k];
    float kcx = g_S[(1*15 + 0)*K_CL + k] / (sk + 1e-6f);
    float kcy = g_S[(1*15 + 1)*K_CL + k] / (sk + 1e-6f);

    float sum0 = 0.f, sum1 = 0.f;
    #pragma unroll
    for (int c = 0; c < NISO; c++) {
        dq[c]  = g_S[(0*15 + 3 + c)*K_CL + k];  sum0 += dq[c];
        dkp[c] = g_S[(1*15 + 3 + c)*K_CL + k];  sum1 += dkp[c];
    }
    #pragma unroll
    for (int c = 0; c < NISO; c++) { dq[c] /= sum0; dkp[c] /= sum1; }

    float sxn = sensor[0], syn = sensor[1];
    float nks  = sqrtf((qcx - sxn)*(qcx - sxn) + (qcy - syn)*(qcy - syn));
    float nkps = sqrtf((kcx - sxn)*(kcx - sxn) + (kcy - syn)*(kcy - syn));

    g_QC[2*k] = qcx; g_QC[2*k+1] = qcy;
    g_KC[2*k] = kcx; g_KC[2*k+1] = kcy;

    for (int o = 0; o < 32; o++) {
        float u = g1b[o], v = 0.f;
        #pragma unroll
        for (int c = 0; c < NISO; c++) {
            u = fmaf(dq[c],  g1w[c*32 + o],          u);
            v = fmaf(dkp[c], g1w[(NISO + c)*32 + o], v);
        }
        g_GU[k*32 + o] = u;
        g_GV[k*32 + o] = v;
        g_HA[k*32 + o] = fmaf(nks, h1w[32 + o], h1b[o]);
        g_HB[k*32 + o] = nkps * h1w[64 + o];
    }
}

// ---------------- kernel 4: R factor ----------------
__launch_bounds__(256)
__global__ void rfactor_k(const float* __restrict__ g2w, const float* __restrict__ g2b,
                          const float* __restrict__ h2w, const float* __restrict__ h2b,
                          const float* __restrict__ h1w)
{
    __shared__ float sGU[32][68], sGV[32][68], sHA[32][68], sHB[32][68];
    __shared__ float sW[96];
    __shared__ float sQC[64][2], sKC[64][2];

    const int tid = threadIdx.x;
    const int ib = blockIdx.y * 64, jb = blockIdx.x * 64;

    #pragma unroll
    for (int p = 0; p < 2; p++) {
        int idx = tid + p * 256;
        int row = idx >> 3, c0 = (idx & 7) * 4;
        float4 u = *(const float4*)&g_GU[(ib + row)*32 + c0];
        sGU[c0][row] = u.x; sGU[c0+1][row] = u.y; sGU[c0+2][row] = u.z; sGU[c0+3][row] = u.w;
        float4 v = *(const float4*)&g_GV[(jb + row)*32 + c0];
        sGV[c0][row] = v.x; sGV[c0+1][row] = v.y; sGV[c0+2][row] = v.z; sGV[c0+3][row] = v.w;
        float4 a = *(const float4*)&g_HA[(ib + row)*32 + c0];
        sHA[c0][row] = a.x; sHA[c0+1][row] = a.y; sHA[c0+2][row] = a.z; sHA[c0+3][row] = a.w;
        float4 b = *(const float4*)&g_HB[(jb + row)*32 + c0];
        sHB[c0][row] = b.x; sHB[c0+1][row] = b.y; sHB[c0+2][row] = b.z; sHB[c0+3][row] = b.w;
    }
    if (tid < 32)       sW[tid] = g2w[tid];
    else if (tid < 64)  sW[tid] = h2w[tid - 32];
    else if (tid < 96)  sW[tid] = h1w[tid - 64];
    if (tid < 128)      sQC[tid >> 1][tid & 1] = g_QC[(ib + (tid >> 1))*2 + (tid & 1)];
    else                { int t = tid - 128; sKC[t >> 1][t & 1] = g_KC[(jb + (t >> 1))*2 + (t & 1)]; }
    __syncthreads();

    const int ty = tid >> 4, tx = tid & 15;
    float nkk[4][4];
    #pragma unroll
    for (int m = 0; m < 4; m++) {
        float qx = sQC[ty*4 + m][0], qy = sQC[ty*4 + m][1];
        #pragma unroll
        for (int n = 0; n < 4; n++) {
            float dx = qx - sKC[tx*4 + n][0], dy = qy - sKC[tx*4 + n][1];
            nkk[m][n] = sqrtf(dx*dx + dy*dy);
        }
    }

    float gacc[4][4], hacc[4][4];
    #pragma unroll
    for (int m = 0; m < 4; m++)
        #pragma unroll
        for (int n = 0; n < 4; n++) { gacc[m][n] = 0.f; hacc[m][n] = 0.f; }

    #pragma unroll 4
    for (int c = 0; c < 32; c++) {
        float gw = sW[c], hw = sW[32 + c], w1c = sW[64 + c];
        float4 au = *(const float4*)&sGU[c][ty*4];
        float4 aa = *(const float4*)&sHA[c][ty*4];
        float4 bv = *(const float4*)&sGV[c][tx*4];
        float4 bb = *(const float4*)&sHB[c][tx*4];
        const float* aup = &au.x; const float* aap = &aa.x;
        const float* bvp = &bv.x; const float* bbp = &bb.x;
        #pragma unroll
        for (int m = 0; m < 4; m++)
            #pragma unroll
            for (int n = 0; n < 4; n++) {
                float g = fmaxf(aup[m] + bvp[n], 0.f);
                gacc[m][n] = fmaf(g, gw, gacc[m][n]);
                float h = fmaxf(fmaf(nkk[m][n], w1c, aap[m] + bbp[n]), 0.f);
                hacc[m][n] = fmaf(h, hw, hacc[m][n]);
            }
    }

    const float g2b0 = g2b[0], h2b0 = h2b[0];
    #pragma unroll
    for (int m = 0; m < 4; m++) {
        float4 o;
        float* op = &o.x;
        #pragma unroll
        for (int n = 0; n < 4; n++)
            op[n] = fmaxf(gacc[m][n] + g2b0, 0.f) * fmaxf(hacc[m][n] + h2b0, 0.f);
        *(float4*)&g_R[(size_t)(ib + ty*4 + m) * K_CL + jb + tx*4] = o;
    }
}

// ---------------- pipelined f32x2 GEMM ----------------
template<int TM, int MODE, bool BT>
__launch_bounds__(256)
__global__ void gemm_k2(const float* __restrict__ A, const float* __restrict__ B,
                        float* __restrict__ C, int M, int N, int Kd,
                        const float* __restrict__ ext, float scale)
{
    constexpr int TN = 64;
    constexpr int RM = TM / 16;
    constexpr int NA = (TM * 4 + 255) / 256;
    __shared__ float As[2][16][TM];
    __shared__ float Bs[2][16][TN];

    const int tid = threadIdx.x;
    const int tx = tid & 15, ty = tid >> 4;
    const int row0 = blockIdx.y * TM, col0 = blockIdx.x * TN;

    float4 ra[NA];
    float4 rb;

    auto ldTile = [&](int k0) {
        #pragma unroll
        for (int i = 0; i < NA; i++) {
            int idx = tid + i * 256;
            if ((TM * 4) % 256 == 0 || idx < TM * 4) {
                int lr = idx >> 2, lc = (idx & 3) * 4;
                ra[i] = *(const float4*)(A + (size_t)(row0 + lr) * Kd + k0 + lc);
            }
        }
        if (BT) {
            int lr = tid >> 2, lc = (tid & 3) * 4;
            rb = *(const float4*)(B + (size_t)(col0 + lr) * Kd + k0 + lc);
        } else {
            int lr = tid >> 4, lc = (tid & 15) * 4;
            rb = *(const float4*)(B + (size_t)(k0 + lr) * N + col0 + lc);
        }
    };
    auto stTile = [&](int buf) {
        #pragma unroll
        for (int i = 0; i < NA; i++) {
            int idx = tid + i * 256;
            if ((TM * 4) % 256 == 0 || idx < TM * 4) {
                int lr = idx >> 2, lc = (idx & 3) * 4;
                As[buf][lc+0][lr] = ra[i].x; As[buf][lc+1][lr] = ra[i].y;
                As[buf][lc+2][lr] = ra[i].z; As[buf][lc+3][lr] = ra[i].w;
            }
        }
        if (BT) {
            int lr = tid >> 2, lc = (tid & 3) * 4;
            Bs[buf][lc+0][lr] = rb.x; Bs[buf][lc+1][lr] = rb.y;
            Bs[buf][lc+2][lr] = rb.z; Bs[buf][lc+3][lr] = rb.w;
        } else {
            int lr = tid >> 4, lc = (tid & 15) * 4;
            *(float4*)&Bs[buf][lr][lc] = rb;
        }
    };

    u64 acc[RM][2];
    #pragma unroll
    for (int m = 0; m < RM; m++) { acc[m][0] = 0ULL; acc[m][1] = 0ULL; }

    const int nt = Kd >> 4;
    ldTile(0);
    stTile(0);
    __syncthreads();

    for (int t = 0; t < nt; t++) {
        const int cur = t & 1;
        if (t + 1 < nt) ldTile((t + 1) << 4);

        #pragma unroll
        for (int kk = 0; kk < 16; kk++) {
            float a[RM];
            if constexpr (RM == 8) {
                float4 t0 = *(const float4*)&As[cur][kk][ty * 8];
                float4 t1 = *(const float4*)&As[cur][kk][ty * 8 + 4];
                a[0]=t0.x; a[1]=t0.y; a[2]=t0.z; a[3]=t0.w;
                a[4]=t1.x; a[5]=t1.y; a[6]=t1.z; a[7]=t1.w;
            } else {
                float2 t0 = *(const float2*)&As[cur][kk][ty * 2];
                a[0]=t0.x; a[1]=t0.y;
            }
            u64 b0 = *(const u64*)&Bs[cur][kk][tx * 4];
            u64 b1 = *(const u64*)&Bs[cur][kk][tx * 4 + 2];
            #pragma unroll
            for (int m = 0; m < RM; m++) {
                u64 aa = pack2(a[m], a[m]);
                acc[m][0] = fma2(aa, b0, acc[m][0]);
                acc[m][1] = fma2(aa, b1, acc[m][1]);
            }
        }

        if (t + 1 < nt) {
            stTile((t + 1) & 1);
            __syncthreads();
        }
    }

    #pragma unroll
    for (int m = 0; m < RM; m++) {
        int i = row0 + ty * RM + m;
        int j0 = col0 + tx * 4;
        float v0, v1, v2, v3;
        unpack2(acc[m][0], v0, v1);
        unpack2(acc[m][1], v2, v3);
        if (MODE == 1) {
            float4 r = *(const float4*)(ext + (size_t)i * N + j0);
            v0 = v0 * scale * r.x; v1 = v1 * scale * r.y;
            v2 = v2 * scale * r.z; v3 = v3 * scale * r.w;
        } else if (MODE == 2) {
            v0 = fmaxf(v0 + ext[j0+0], 0.f); v1 = fmaxf(v1 + ext[j0+1], 0.f);
            v2 = fmaxf(v2 + ext[j0+2], 0.f); v3 = fmaxf(v3 + ext[j0+3], 0.f);
        } else if (MODE == 3) {
            v0 += ext[j0+0]; v1 += ext[j0+1]; v2 += ext[j0+2]; v3 += ext[j0+3];
        }
        float4 o; o.x = v0; o.y = v1; o.z = v2; o.w = v3;
        *(float4*)(C + (size_t)i * N + j0) = o;
    }
}

// ---------------- softmax ----------------
__global__ void softmax_k(float* __restrict__ X)
{
    const int row = blockIdx.x, tid = threadIdx.x;
    __shared__ float red[256];
    float v[4];
    float m = -3.4e38f;
    #pragma unroll
    for (int j = 0; j < 4; j++) { v[j] = X[(size_t)row * K_CL + tid + j * 256]; m = fmaxf(m, v[j]); }
    red[tid] = m; __syncthreads();
    #pragma unroll
    for (int s = 128; s > 0; s >>= 1) { if (tid < s) red[tid] = fmaxf(red[tid], red[tid + s]); __syncthreads(); }
    m = red[0]; __syncthreads();
    float sum = 0.f;
    #pragma unroll
    for (int j = 0; j < 4; j++) { v[j] = __expf(v[j] - m); sum += v[j]; }
    red[tid] = sum; __syncthreads();
    #pragma unroll
    for (int s = 128; s > 0; s >>= 1) { if (tid < s) red[tid] += red[tid + s]; __syncthreads(); }
    float inv = 1.f / red[0];
    #pragma unroll
    for (int j = 0; j < 4; j++) X[(size_t)row * K_CL + tid + j * 256] = v[j] * inv;
}

// ---------------- residual add + LayerNorm ----------------
__global__ void add_ln_k(const float* __restrict__ a, const float* __restrict__ b,
                         const float* __restrict__ g, const float* __restrict__ be,
                         float* __restrict__ out)
{
    const int row = blockIdx.x, tid = threadIdx.x;
    __shared__ float red[256];
    float x = a[row * DM + tid] + b[row * DM + tid];
    red[tid] = x; __syncthreads();
    #pragma unroll
    for (int s = 128; s > 0; s >>= 1) { if (tid < s) red[tid] += red[tid + s]; __syncthreads(); }
    float mean = red[0] * (1.f / DM); __syncthreads();
    float d = x - mean;
    red[tid] = d * d; __syncthreads();
    #pragma unroll
    for (int s = 128; s > 0; s >>= 1) { if (tid < s) red[tid] += red[tid + s]; __syncthreads(); }
    float var = red[0] * (1.f / DM);
    out[row * DM + tid] = d * rsqrtf(var + 1e-6f) * g[tid] + be[tid];
}

// ---------------- launch ----------------
extern "C" void kernel_launch(void* const* d_in, const int* in_sizes, int n_in,
                              void* d_out, int out_size)
{
    const float* sensor = (const float*)d_in[0];
    const float* query  = (const float*)d_in[1];
    const float* keyemb = (const float*)d_in[2];
    const float* qA     = (const float*)d_in[3];
    const float* kA     = (const float*)d_in[4];
    const float* qco    = (const float*)d_in[5];
    const float* kco    = (const float*)d_in[6];
    const int*   qiso   = (const int*)d_in[7];
    const int*   kiso   = (const int*)d_in[8];
    const float* g1w    = (const float*)d_in[9];
    const float* g1b    = (const float*)d_in[10];
    const float* g2w    = (const float*)d_in[11];
    const float* g2b    = (const float*)d_in[12];
    const float* h1w    = (const float*)d_in[13];
    const float* h1b    = (const float*)d_in[14];
    const float* h2w    = (const float*)d_in[15];
    const float* h2b    = (const float*)d_in[16];
    const float* f1w    = (const float*)d_in[17];
    const float* f1b    = (const float*)d_in[18];
    const float* f2w    = (const float*)d_in[19];
    const float* f2b    = (const float*)d_in[20];
    const float* ln1g   = (const float*)d_in[21];
    const float* ln1b   = (const float*)d_in[22];
    const float* ln2g   = (const float*)d_in[23];
    const float* ln2b   = (const float*)d_in[24];
    float* out = (float*)d_out;

    float *pR, *pL, *pAO, *pX, *pF1, *pF2;
    cudaGetSymbolAddress((void**)&pR,  g_R);
    cudaGetSymbolAddress((void**)&pL,  g_L);
    cudaGetSymbolAddress((void**)&pAO, g_AO);
    cudaGetSymbolAddress((void**)&pX,  g_X);
    cudaGetSymbolAddress((void**)&pF1, g_F1);
    cudaGetSymbolAddress((void**)&pF2, g_F2);

    // counting sort of pixel rows by iso bucket (deterministic, no atomics)
    hist_k<<<dim3(HBLK, 2), 256>>>(qiso, kiso);
    offsets_k<<<1, 256>>>();
    scatter_k<<<dim3(HBLK, 2), 256>>>(qiso, kiso);

    // fused transposed reductions (register-only accumulation)
    reduce_k<<<dim3(RBLK, 2), 256>>>(qA, kA, qco, kco);
    reduce2_k<<<(2 * 15 * K_CL) / 256, 256>>>();
    cfeat_k<<<K_CL / 256, 256>>>(sensor, g1w, g1b, h1w, h1b);
    rfactor_k<<<dim3(16, 16), 256>>>(g2w, g2b, h2w, h2b, h1w);

    // logits = (Q @ K^T)/16 * R
    gemm_k2<128, 1, true><<<dim3(16, 8), 256>>>(query, keyemb, pL, K_CL, K_CL, DM, pR, 0.0625f);
    softmax_k<<<K_CL, 256>>>(pL);
    // attn @ key_emb
    gemm_k2<32, 0, false><<<dim3(4, 32), 256>>>(pL, keyemb, pAO, K_CL, DM, K_CL, nullptr, 1.f);
    add_ln_k<<<K_CL, 256>>>(query, pAO, ln1g, ln1b, pX);
    // FFN1
    gemm_k2<128, 2, false><<<dim3(16, 8), 256>>>(pX, f1w, pF1, K_CL, 4 * DM, DM, f1b, 1.f);
    // FFN2
    gemm_k2<32, 3, false><<<dim3(4, 32), 256>>>(pF1, f2w, pF2, K_CL, DM, 4 * DM, f2b, 1.f);
    add_ln_k<<<K_CL, 256>>>(pX, pF2, ln2g, ln2b, out);
}